// round 14
// baseline (speedup 1.0000x reference)
#include <cuda_runtime.h>
#include <math.h>
#include <stdint.h>

#define B_   2
#define T_   2048
#define C_   768
#define H_   12
#define DH_  64
#define LOG2E 1.4426950408889634f
#define SKF  20   // float row stride for projection GEMMs (16 data + 4 pad)

// fused-attn smem strides
#define SQK  68   // Q/K tile stride (64 data + 4)  -> 4r+c conflict-free frags
#define SVV  72   // V tile k-major stride (64 + 8) -> 8c+r conflict-free frags
#define SSS  132  // S tile stride (128 + 4)        -> 4r+c conflict-free frags

// smem float offsets for fused kernel
#define OFF_Q     0
#define OFF_K     (128 * SQK)                    // 8704
#define OFF_V     (OFF_K + 128 * SQK)            // 17408
#define OFF_S     (OFF_V + 2 * 128 * SVV)        // 35840
#define OFF_ILS   (OFF_S + 128 * SSS)            // 52736
#define OFF_SPART (OFF_ILS + 128)                // 52864
#define SMEM_FLOATS (OFF_SPART + 512)            // 53376
#define SMEM_BYTES  (SMEM_FLOATS * 4)            // 213504

// Scratch (device globals — no allocation allowed)
__device__ float g_q[B_ * T_ * C_];
__device__ float g_k[B_ * T_ * C_];
__device__ float g_v[B_ * T_ * C_];
__device__ float g_att[B_ * T_ * C_];
__device__ float g_invsum[B_ * H_ * T_];

// ---------------------------------------------------------------------------
__device__ __forceinline__ uint32_t f2tf(float v) {   // rounded tf32
    uint32_t r;
    asm("cvt.rna.tf32.f32 %0, %1;" : "=r"(r) : "f"(v));
    return r;
}
__device__ __forceinline__ void mma8(float4& d, const uint32_t* a, const uint32_t* b) {
    asm("mma.sync.aligned.m16n8k8.row.col.f32.tf32.tf32.f32 "
        "{%0,%1,%2,%3}, {%4,%5,%6,%7}, {%8,%9}, {%0,%1,%2,%3};"
        : "+f"(d.x), "+f"(d.y), "+f"(d.z), "+f"(d.w)
        : "r"(a[0]), "r"(a[1]), "r"(a[2]), "r"(a[3]), "r"(b[0]), "r"(b[1]));
}
// consumer-side exact split: hi = raw fp32 bits (HW reads top 19), lo exact.
__device__ __forceinline__ void split_lo(float v, uint32_t& hi, uint32_t& lo) {
    hi = __float_as_uint(v);
    lo = __float_as_uint(v - __uint_as_float(hi & 0xFFFFE000u));
}
__device__ __forceinline__ void cp16(void* smem_dst, const void* gsrc) {
    uint32_t s = (uint32_t)__cvta_generic_to_shared(smem_dst);
    asm volatile("cp.async.cg.shared.global [%0], [%1], 16;" :: "r"(s), "l"(gsrc));
}
#define CP_COMMIT asm volatile("cp.async.commit_group;")
#define CP_WAIT1  asm volatile("cp.async.wait_group 1;")
#define CP_WAIT0  asm volatile("cp.async.wait_group 0;")

// ---------------------------------------------------------------------------
// 2-term NT GEMM (A exact hi+lo split, B rounded hi-only), cp.async pipeline.
// ---------------------------------------------------------------------------
__device__ __forceinline__ void gemm2_body(const float* __restrict__ A,
                                           const float* __restrict__ Bm,
                                           float* __restrict__ C,
                                           int K, int lda, int ldb, int ldc,
                                           int m0, int n0) {
    __shared__ float As[2][128][SKF], Bs[2][128][SKF];
    const int tid = threadIdx.x;
    const int warp = tid >> 5, lane = tid & 31;
    const int wm = (warp >> 2) * 64, wn = (warp & 3) * 32;
    const int r = lane >> 2, c = lane & 3;
    const int row0 = tid >> 2, ko0 = (tid & 3) << 2;
    const int row1 = row0 + 64;

    float4 acc[4][4];
#pragma unroll
    for (int i = 0; i < 4; i++)
#pragma unroll
        for (int j = 0; j < 4; j++) acc[i][j] = make_float4(0, 0, 0, 0);

    const int niter = K / 16;
    cp16(&As[0][row0][ko0], A + (size_t)(m0 + row0) * lda + ko0);
    cp16(&As[0][row1][ko0], A + (size_t)(m0 + row1) * lda + ko0);
    cp16(&Bs[0][row0][ko0], Bm + (size_t)(n0 + row0) * ldb + ko0);
    cp16(&Bs[0][row1][ko0], Bm + (size_t)(n0 + row1) * ldb + ko0);
    CP_COMMIT;

    for (int it = 0; it < niter; it++) {
        if (it + 1 < niter) {
            int kn = (it + 1) * 16;
            int s = (it + 1) & 1;
            cp16(&As[s][row0][ko0], A + (size_t)(m0 + row0) * lda + kn + ko0);
            cp16(&As[s][row1][ko0], A + (size_t)(m0 + row1) * lda + kn + ko0);
            cp16(&Bs[s][row0][ko0], Bm + (size_t)(n0 + row0) * ldb + kn + ko0);
            cp16(&Bs[s][row1][ko0], Bm + (size_t)(n0 + row1) * ldb + kn + ko0);
            CP_COMMIT;
            CP_WAIT1;
        } else {
            CP_WAIT0;
        }
        __syncthreads();
        const float (*Af)[SKF] = As[it & 1];
        const float (*Bf)[SKF] = Bs[it & 1];
#pragma unroll
        for (int kb = 0; kb < 16; kb += 8) {
            uint32_t bh[4][2];
#pragma unroll
            for (int nj = 0; nj < 4; nj++) {
                int col = wn + nj * 8 + r;
                bh[nj][0] = f2tf(Bf[col][kb + c]);
                bh[nj][1] = f2tf(Bf[col][kb + c + 4]);
            }
#pragma unroll
            for (int mi = 0; mi < 4; mi++) {
                int rw = wm + mi * 16 + r;
                uint32_t ah[4], al[4];
                split_lo(Af[rw][kb + c],         ah[0], al[0]);
                split_lo(Af[rw + 8][kb + c],     ah[1], al[1]);
                split_lo(Af[rw][kb + c + 4],     ah[2], al[2]);
                split_lo(Af[rw + 8][kb + c + 4], ah[3], al[3]);
#pragma unroll
                for (int nj = 0; nj < 4; nj++) {
                    mma8(acc[mi][nj], al, bh[nj]);
                    mma8(acc[mi][nj], ah, bh[nj]);
                }
            }
        }
        __syncthreads();
    }
#pragma unroll
    for (int mi = 0; mi < 4; mi++)
#pragma unroll
        for (int nj = 0; nj < 4; nj++) {
            int gm = m0 + wm + mi * 16 + r;
            int gn = n0 + wn + nj * 8 + 2 * c;
            *(float2*)&C[(size_t)gm * ldc + gn]       = make_float2(acc[mi][nj].x, acc[mi][nj].y);
            *(float2*)&C[(size_t)(gm + 8) * ldc + gn] = make_float2(acc[mi][nj].z, acc[mi][nj].w);
        }
}

// Fused QKV projection: grid (18, 32)
__global__ void __launch_bounds__(256) gemm_qkv(const float* __restrict__ x,
                                                const float* __restrict__ wq,
                                                const float* __restrict__ wk,
                                                const float* __restrict__ wv,
                                                float* __restrict__ q,
                                                float* __restrict__ k,
                                                float* __restrict__ v) {
    const int nb = blockIdx.x;
    const int sel = nb / 6;
    const int n0 = (nb % 6) * 128;
    const int m0 = blockIdx.y * 128;
    const float* W = (sel == 0) ? wq : (sel == 1) ? wk : wv;
    float* O = (sel == 0) ? q : (sel == 1) ? k : v;
    gemm2_body(x, W, O, C_, C_, C_, C_, m0, n0);
}

// Final projection: grid (6, 32)
__global__ void __launch_bounds__(256) gemm_final(const float* __restrict__ A,
                                                  const float* __restrict__ Wo,
                                                  float* __restrict__ C) {
    gemm2_body(A, Wo, C, C_, C_, C_, C_, blockIdx.y * 128, blockIdx.x * 128);
}

// ---------------------------------------------------------------------------
// Fused attention: per (z, mt) CTA computes S = exp(0.125*QK^T) tile-by-tile,
// writes unnormalized e to W (weights), accumulates O = e@V, scales O by
// 1/rowsum at the end, writes O and invsum. Zero-fills masked weight columns.
// grid (16, 24): mt = 15 - bx (heavy first), z = by. Dynamic smem SMEM_BYTES.
// ---------------------------------------------------------------------------
__global__ void __launch_bounds__(256, 1) fused_attn(const float* __restrict__ Q,
                                                     const float* __restrict__ Kg,
                                                     const float* __restrict__ V,
                                                     float* __restrict__ W,
                                                     float* __restrict__ O,
                                                     float* __restrict__ invsum) {
    extern __shared__ float sm[];
    float* Qs = sm + OFF_Q;            // [128][SQK]
    float* Ks = sm + OFF_K;            // [128][SQK]
    float* Vs = sm + OFF_V;            // [2][128][SVV]
    float* Ss = sm + OFF_S;            // [128][SSS]
    float* ils = sm + OFF_ILS;         // [128]
    float* spart = sm + OFF_SPART;     // [128][4]

    const int mt = 15 - blockIdx.x;
    const int z = blockIdx.y;
    const int b = z / H_, h = z % H_;
    const int m0 = mt * 128;
    const int tid = threadIdx.x;
    const int warp = tid >> 5, lane = tid & 31;
    const int wm = (warp >> 2) * 64;
    const int wn = (warp & 3) * 32;    // QK col group
    const int wn2 = (warp & 3) * 16;   // PV col group
    const int r = lane >> 2, c = lane & 3;

    float* Wz = W + (size_t)z * T_ * T_;
    const float* Qp = Q + (size_t)b * T_ * C_ + h * DH_;
    const float* Kp = Kg + (size_t)b * T_ * C_ + h * DH_;
    const float* Vp = V + (size_t)b * T_ * C_ + h * DH_;

    // Preload Q tile + K0 + V0 (each: 2048 16B chunks, 8 per thread)
#pragma unroll
    for (int it = 0; it < 8; it++) {
        int idx = tid + it * 256;
        int row = idx >> 4, pos = (idx & 15) << 2;
        cp16(&Qs[row * SQK + pos], Qp + (size_t)(m0 + row) * C_ + pos);
    }
#pragma unroll
    for (int it = 0; it < 8; it++) {
        int idx = tid + it * 256;
        int row = idx >> 4, pos = (idx & 15) << 2;
        cp16(&Ks[row * SQK + pos], Kp + (size_t)row * C_ + pos);
        cp16(&Vs[row * SVV + pos], Vp + (size_t)row * C_ + pos);
    }
    CP_COMMIT;

    // Zero-fill masked weight columns for this row block (cols >= (mt+1)*128)
    {
        const int zc4 = (mt + 1) * 32;   // first zero float4 index per row
        const float4 zz = make_float4(0, 0, 0, 0);
        for (int row = 0; row < 128; row++) {
            float4* dst = (float4*)(Wz + (size_t)(m0 + row) * T_);
            for (int c4 = zc4 + tid; c4 < 512; c4 += 256) dst[c4] = zz;
        }
    }

    float4 accO[4][2];
#pragma unroll
    for (int i = 0; i < 4; i++)
#pragma unroll
        for (int j = 0; j < 2; j++) accO[i][j] = make_float4(0, 0, 0, 0);
    float se0[4] = {0, 0, 0, 0}, se1[4] = {0, 0, 0, 0};

    for (int kt = 0; kt <= mt; kt++) {
        CP_WAIT0;
        __syncthreads();

        // ---- QK phase: accS = Q[m0 tile] . K[kt tile]^T ----
        float4 accS[4][4];
#pragma unroll
        for (int i = 0; i < 4; i++)
#pragma unroll
            for (int j = 0; j < 4; j++) accS[i][j] = make_float4(0, 0, 0, 0);

#pragma unroll
        for (int kb = 0; kb < DH_; kb += 8) {
            uint32_t bh[4][2];
#pragma unroll
            for (int nj = 0; nj < 4; nj++) {
                int col = wn + nj * 8 + r;
                bh[nj][0] = f2tf(Ks[col * SQK + kb + c]);
                bh[nj][1] = f2tf(Ks[col * SQK + kb + c + 4]);
            }
#pragma unroll
            for (int mi = 0; mi < 4; mi++) {
                int rw = wm + mi * 16 + r;
                uint32_t ah[4], al[4];
                split_lo(Qs[rw * SQK + kb + c],         ah[0], al[0]);
                split_lo(Qs[(rw + 8) * SQK + kb + c],   ah[1], al[1]);
                split_lo(Qs[rw * SQK + kb + c + 4],     ah[2], al[2]);
                split_lo(Qs[(rw + 8) * SQK + kb + c + 4], ah[3], al[3]);
#pragma unroll
                for (int nj = 0; nj < 4; nj++) {
                    mma8(accS[mi][nj], al, bh[nj]);
                    mma8(accS[mi][nj], ah, bh[nj]);
                }
            }
        }

        // ---- epilogue: e = exp(0.125*s) (masked->0); write e to W + S smem ----
        const bool diag = (kt == mt);
        const int cbase = kt * 128;
#pragma unroll
        for (int mi = 0; mi < 4; mi++) {
            int lm = wm + mi * 16 + r;
#pragma unroll
            for (int nj = 0; nj < 4; nj++) {
                int ln = wn + nj * 8 + 2 * c;
                float e0 = exp2f(0.125f * LOG2E * accS[mi][nj].x);
                float e1 = exp2f(0.125f * LOG2E * accS[mi][nj].y);
                float e2 = exp2f(0.125f * LOG2E * accS[mi][nj].z);
                float e3 = exp2f(0.125f * LOG2E * accS[mi][nj].w);
                if (diag) {
                    if (ln > lm) e0 = 0.0f;
                    if (ln + 1 > lm) e1 = 0.0f;
                    if (ln > lm + 8) e2 = 0.0f;
                    if (ln + 1 > lm + 8) e3 = 0.0f;
                }
                se0[mi] += e0 + e1;
                se1[mi] += e2 + e3;
                *(float2*)&Wz[(size_t)(m0 + lm) * T_ + cbase + ln]     = make_float2(e0, e1);
                *(float2*)&Wz[(size_t)(m0 + lm + 8) * T_ + cbase + ln] = make_float2(e2, e3);
                *(float2*)&Ss[lm * SSS + ln]       = make_float2(e0, e1);
                *(float2*)&Ss[(lm + 8) * SSS + ln] = make_float2(e2, e3);
            }
        }
        __syncthreads();   // S visible; K consumed by all

        // prefetch next K/V (K buffer free; V into other buffer)
        if (kt < mt) {
            const int kn = (kt + 1) * 128;
            float* Vb = Vs + ((kt + 1) & 1) * 128 * SVV;
#pragma unroll
            for (int it = 0; it < 8; it++) {
                int idx = tid + it * 256;
                int row = idx >> 4, pos = (idx & 15) << 2;
                cp16(&Ks[row * SQK + pos], Kp + (size_t)(kn + row) * C_ + pos);
                cp16(&Vb[row * SVV + pos], Vp + (size_t)(kn + row) * C_ + pos);
            }
            CP_COMMIT;
        }

        // ---- PV phase: accO += e . V[kt] ----
        const float* Vf = Vs + (kt & 1) * 128 * SVV;
#pragma unroll
        for (int kb = 0; kb < 128; kb += 8) {
            uint32_t bh[2][2];
#pragma unroll
            for (int nj = 0; nj < 2; nj++) {
                int col = wn2 + nj * 8 + r;
                bh[nj][0] = f2tf(Vf[(kb + c) * SVV + col]);
                bh[nj][1] = f2tf(Vf[(kb + c + 4) * SVV + col]);
            }
#pragma unroll
            for (int mi = 0; mi < 4; mi++) {
                int rw = wm + mi * 16 + r;
                uint32_t ah[4], al[4];
                split_lo(Ss[rw * SSS + kb + c],           ah[0], al[0]);
                split_lo(Ss[(rw + 8) * SSS + kb + c],     ah[1], al[1]);
                split_lo(Ss[rw * SSS + kb + c + 4],       ah[2], al[2]);
                split_lo(Ss[(rw + 8) * SSS + kb + c + 4], ah[3], al[3]);
#pragma unroll
                for (int nj = 0; nj < 2; nj++) {
                    mma8(accO[mi][nj], al, bh[nj]);
                    mma8(accO[mi][nj], ah, bh[nj]);
                }
            }
        }
    }

    // ---- row sums -> invsum; scale O; write out ----
#pragma unroll
    for (int mi = 0; mi < 4; mi++) {
        float s0 = se0[mi], s1 = se1[mi];
        s0 += __shfl_xor_sync(0xffffffffu, s0, 1);
        s0 += __shfl_xor_sync(0xffffffffu, s0, 2);
        s1 += __shfl_xor_sync(0xffffffffu, s1, 1);
        s1 += __shfl_xor_sync(0xffffffffu, s1, 2);
        if (c == 0) {
            spart[(wm + mi * 16 + r) * 4 + (warp & 3)]     = s0;
            spart[(wm + mi * 16 + r + 8) * 4 + (warp & 3)] = s1;
        }
    }
    __syncthreads();
    if (tid < 128) {
        float s = spart[tid * 4] + spart[tid * 4 + 1] + spart[tid * 4 + 2] + spart[tid * 4 + 3];
        float il = 1.0f / s;
        ils[tid] = il;
        invsum[(size_t)z * T_ + m0 + tid] = il;
    }
    __syncthreads();

#pragma unroll
    for (int mi = 0; mi < 4; mi++)
#pragma unroll
        for (int nj = 0; nj < 2; nj++) {
            int lm = wm + mi * 16 + r;
            int gn = wn2 + nj * 8 + 2 * c;
            float il0 = ils[lm], il1 = ils[lm + 8];
            *(float2*)&O[(size_t)(b * T_ + m0 + lm) * C_ + h * DH_ + gn] =
                make_float2(accO[mi][nj].x * il0, accO[mi][nj].y * il0);
            *(float2*)&O[(size_t)(b * T_ + m0 + lm + 8) * C_ + h * DH_ + gn] =
                make_float2(accO[mi][nj].z * il1, accO[mi][nj].w * il1);
        }
}

// ---------------------------------------------------------------------------
// Normalize weights in place (reads invsum). One block (128 thr) per row.
// ---------------------------------------------------------------------------
__global__ void __launch_bounds__(128) normalize_kernel(float* __restrict__ W,
                                                        const float* __restrict__ invsum) {
    const int rg = blockIdx.x;
    const int i = rg % T_;
    const float il = invsum[rg];
    const int n4 = (i + 4) >> 2;
    float4* row = (float4*)(W + (size_t)rg * T_);
    for (int j = threadIdx.x; j < n4; j += 128) {
        float4 v = row[j];
        v.x *= il; v.y *= il; v.z *= il; v.w *= il;
        row[j] = v;
    }
}

// ---------------------------------------------------------------------------
extern "C" void kernel_launch(void* const* d_in, const int* in_sizes, int n_in,
                              void* d_out, int out_size) {
    const float* x   = (const float*)d_in[0];
    const float* w_q = (const float*)d_in[1];
    const float* w_k = (const float*)d_in[2];
    const float* w_v = (const float*)d_in[3];
    const float* w_o = (const float*)d_in[4];

    float* qp; cudaGetSymbolAddress((void**)&qp, g_q);
    float* kp; cudaGetSymbolAddress((void**)&kp, g_k);
    float* vp; cudaGetSymbolAddress((void**)&vp, g_v);
    float* ap; cudaGetSymbolAddress((void**)&ap, g_att);
    float* ip; cudaGetSymbolAddress((void**)&ip, g_invsum);

    float* final_out = (float*)d_out;                       // [B,T,C]
    float* w_out = (float*)d_out + (size_t)B_ * T_ * C_;    // [B,H,T,T]

    static int smem_set = 0;
    if (!smem_set) {
        cudaFuncSetAttribute(fused_attn, cudaFuncAttributeMaxDynamicSharedMemorySize,
                             SMEM_BYTES);
        smem_set = 1;
    }

    const dim3 blk(256);

    gemm_qkv<<<dim3(18, 32), blk>>>(x, w_q, w_k, w_v, qp, kp, vp);

    fused_attn<<<dim3(16, 24), blk, SMEM_BYTES>>>(qp, kp, vp, w_out, ap, ip);

    normalize_kernel<<<B_ * H_ * T_, 128>>>(w_out, ip);

    gemm_final<<<dim3(6, 32), blk>>>(ap, w_o, final_out);
}

// round 15
// speedup vs baseline: 1.1222x; 1.1222x over previous
#include <cuda_runtime.h>
#include <math.h>
#include <stdint.h>

#define B_   2
#define T_   2048
#define C_   768
#define H_   12
#define DH_  64
#define LOG2E 1.4426950408889634f
#define SKF  20   // float row stride (16 data + 4 pad) -> conflict-free frag LDS
#define SVF  72   // V k-major row stride (64 data + 8 pad)

// Scratch (device globals — no allocation allowed)
__device__ float g_q[B_ * T_ * C_];
__device__ float g_k[B_ * T_ * C_];
__device__ float g_v[B_ * T_ * C_];
__device__ float g_att[B_ * T_ * C_];
__device__ float g_partial[B_ * H_ * T_ * 16];
__device__ float g_invsum[B_ * H_ * T_];
__device__ float g_pvpart[B_ * H_ * 16 * 4 * 128 * DH_];

// ---------------------------------------------------------------------------
__device__ __forceinline__ uint32_t f2tf(float v) {
    uint32_t r;
    asm("cvt.rna.tf32.f32 %0, %1;" : "=r"(r) : "f"(v));
    return r;
}
__device__ __forceinline__ void mma8(float4& d, const uint32_t* a, const uint32_t* b) {
    asm("mma.sync.aligned.m16n8k8.row.col.f32.tf32.tf32.f32 "
        "{%0,%1,%2,%3}, {%4,%5,%6,%7}, {%8,%9}, {%0,%1,%2,%3};"
        : "+f"(d.x), "+f"(d.y), "+f"(d.z), "+f"(d.w)
        : "r"(a[0]), "r"(a[1]), "r"(a[2]), "r"(a[3]), "r"(b[0]), "r"(b[1]));
}
__device__ __forceinline__ void split_lo(float v, uint32_t& hi, uint32_t& lo) {
    hi = __float_as_uint(v);
    lo = __float_as_uint(v - __uint_as_float(hi & 0xFFFFE000u));
}
__device__ __forceinline__ void cp16(void* smem_dst, const void* gsrc) {
    uint32_t s = (uint32_t)__cvta_generic_to_shared(smem_dst);
    asm volatile("cp.async.cg.shared.global [%0], [%1], 16;" :: "r"(s), "l"(gsrc));
}
#define CP_COMMIT asm volatile("cp.async.commit_group;")
#define CP_WAIT1  asm volatile("cp.async.wait_group 1;")
#define CP_WAIT0  asm volatile("cp.async.wait_group 0;")

// ---------------------------------------------------------------------------
// 2-term NT GEMM (A exact hi+lo split, B rounded hi-only), cp.async pipeline.
// ---------------------------------------------------------------------------
__device__ __forceinline__ void gemm2_body(const float* __restrict__ A,
                                           const float* __restrict__ Bm,
                                           float* __restrict__ C,
                                           int K, int lda, int ldb, int ldc,
                                           int m0, int n0) {
    __shared__ float As[2][128][SKF], Bs[2][128][SKF];
    const int tid = threadIdx.x;
    const int warp = tid >> 5, lane = tid & 31;
    const int wm = (warp >> 2) * 64, wn = (warp & 3) * 32;
    const int r = lane >> 2, c = lane & 3;
    const int row0 = tid >> 2, ko0 = (tid & 3) << 2;
    const int row1 = row0 + 64;

    float4 acc[4][4];
#pragma unroll
    for (int i = 0; i < 4; i++)
#pragma unroll
        for (int j = 0; j < 4; j++) acc[i][j] = make_float4(0, 0, 0, 0);

    const int niter = K / 16;
    cp16(&As[0][row0][ko0], A + (size_t)(m0 + row0) * lda + ko0);
    cp16(&As[0][row1][ko0], A + (size_t)(m0 + row1) * lda + ko0);
    cp16(&Bs[0][row0][ko0], Bm + (size_t)(n0 + row0) * ldb + ko0);
    cp16(&Bs[0][row1][ko0], Bm + (size_t)(n0 + row1) * ldb + ko0);
    CP_COMMIT;

    for (int it = 0; it < niter; it++) {
        if (it + 1 < niter) {
            int kn = (it + 1) * 16;
            int s = (it + 1) & 1;
            cp16(&As[s][row0][ko0], A + (size_t)(m0 + row0) * lda + kn + ko0);
            cp16(&As[s][row1][ko0], A + (size_t)(m0 + row1) * lda + kn + ko0);
            cp16(&Bs[s][row0][ko0], Bm + (size_t)(n0 + row0) * ldb + kn + ko0);
            cp16(&Bs[s][row1][ko0], Bm + (size_t)(n0 + row1) * ldb + kn + ko0);
            CP_COMMIT;
            CP_WAIT1;
        } else {
            CP_WAIT0;
        }
        __syncthreads();
        const float (*Af)[SKF] = As[it & 1];
        const float (*Bf)[SKF] = Bs[it & 1];
#pragma unroll
        for (int kb = 0; kb < 16; kb += 8) {
            uint32_t bh[4][2];
#pragma unroll
            for (int nj = 0; nj < 4; nj++) {
                int col = wn + nj * 8 + r;
                bh[nj][0] = f2tf(Bf[col][kb + c]);
                bh[nj][1] = f2tf(Bf[col][kb + c + 4]);
            }
#pragma unroll
            for (int mi = 0; mi < 4; mi++) {
                int rw = wm + mi * 16 + r;
                uint32_t ah[4], al[4];
                split_lo(Af[rw][kb + c],         ah[0], al[0]);
                split_lo(Af[rw + 8][kb + c],     ah[1], al[1]);
                split_lo(Af[rw][kb + c + 4],     ah[2], al[2]);
                split_lo(Af[rw + 8][kb + c + 4], ah[3], al[3]);
#pragma unroll
                for (int nj = 0; nj < 4; nj++) {
                    mma8(acc[mi][nj], al, bh[nj]);
                    mma8(acc[mi][nj], ah, bh[nj]);
                }
            }
        }
        __syncthreads();
    }
#pragma unroll
    for (int mi = 0; mi < 4; mi++)
#pragma unroll
        for (int nj = 0; nj < 4; nj++) {
            int gm = m0 + wm + mi * 16 + r;
            int gn = n0 + wn + nj * 8 + 2 * c;
            *(float2*)&C[(size_t)gm * ldc + gn]       = make_float2(acc[mi][nj].x, acc[mi][nj].y);
            *(float2*)&C[(size_t)(gm + 8) * ldc + gn] = make_float2(acc[mi][nj].z, acc[mi][nj].w);
        }
}

// Fused QKV projection (2-term): grid (18, 32)
__global__ void __launch_bounds__(256) gemm_qkv(const float* __restrict__ x,
                                                const float* __restrict__ wq,
                                                const float* __restrict__ wk,
                                                const float* __restrict__ wv,
                                                float* __restrict__ q,
                                                float* __restrict__ k,
                                                float* __restrict__ v) {
    const int nb = blockIdx.x;
    const int sel = nb / 6;
    const int n0 = (nb % 6) * 128;
    const int m0 = blockIdx.y * 128;
    const float* W = (sel == 0) ? wq : (sel == 1) ? wk : wv;
    float* O = (sel == 0) ? q : (sel == 1) ? k : v;
    gemm2_body(x, W, O, C_, C_, C_, C_, m0, n0);
}

// ---------------------------------------------------------------------------
// Final projection, 128x64 tiles (2-term): grid (12, 32). 8 warps as 4x2.
// ---------------------------------------------------------------------------
__global__ void __launch_bounds__(256) gemm_final64(const float* __restrict__ A,
                                                    const float* __restrict__ Wo,
                                                    float* __restrict__ C) {
    __shared__ float As[2][128][SKF], Bs[2][64][SKF];
    const int m0 = blockIdx.y * 128, n0 = blockIdx.x * 64;
    const int tid = threadIdx.x;
    const int warp = tid >> 5, lane = tid & 31;
    const int wm = (warp >> 1) * 32, wn = (warp & 1) * 32;
    const int r = lane >> 2, c = lane & 3;
    const int row0 = tid >> 2, ko0 = (tid & 3) << 2;
    const int row1 = row0 + 64;

    float4 acc[2][4];
#pragma unroll
    for (int i = 0; i < 2; i++)
#pragma unroll
        for (int j = 0; j < 4; j++) acc[i][j] = make_float4(0, 0, 0, 0);

    const int niter = C_ / 16;
    cp16(&As[0][row0][ko0], A + (size_t)(m0 + row0) * C_ + ko0);
    cp16(&As[0][row1][ko0], A + (size_t)(m0 + row1) * C_ + ko0);
    if (row0 < 64) cp16(&Bs[0][row0][ko0], Wo + (size_t)(n0 + row0) * C_ + ko0);
    CP_COMMIT;

    for (int it = 0; it < niter; it++) {
        if (it + 1 < niter) {
            int kn = (it + 1) * 16;
            int s = (it + 1) & 1;
            cp16(&As[s][row0][ko0], A + (size_t)(m0 + row0) * C_ + kn + ko0);
            cp16(&As[s][row1][ko0], A + (size_t)(m0 + row1) * C_ + kn + ko0);
            if (row0 < 64) cp16(&Bs[s][row0][ko0], Wo + (size_t)(n0 + row0) * C_ + kn + ko0);
            CP_COMMIT;
            CP_WAIT1;
        } else {
            CP_WAIT0;
        }
        __syncthreads();
        const float (*Af)[SKF] = As[it & 1];
        const float (*Bf)[SKF] = Bs[it & 1];
#pragma unroll
        for (int kb = 0; kb < 16; kb += 8) {
            uint32_t bh[4][2];
#pragma unroll
            for (int nj = 0; nj < 4; nj++) {
                int col = wn + nj * 8 + r;
                bh[nj][0] = f2tf(Bf[col][kb + c]);
                bh[nj][1] = f2tf(Bf[col][kb + c + 4]);
            }
#pragma unroll
            for (int mi = 0; mi < 2; mi++) {
                int rw = wm + mi * 16 + r;
                uint32_t ah[4], al[4];
                split_lo(Af[rw][kb + c],         ah[0], al[0]);
                split_lo(Af[rw + 8][kb + c],     ah[1], al[1]);
                split_lo(Af[rw][kb + c + 4],     ah[2], al[2]);
                split_lo(Af[rw + 8][kb + c + 4], ah[3], al[3]);
#pragma unroll
                for (int nj = 0; nj < 4; nj++) {
                    mma8(acc[mi][nj], al, bh[nj]);
                    mma8(acc[mi][nj], ah, bh[nj]);
                }
            }
        }
        __syncthreads();
    }
#pragma unroll
    for (int mi = 0; mi < 2; mi++)
#pragma unroll
        for (int nj = 0; nj < 4; nj++) {
            int gm = m0 + wm + mi * 16 + r;
            int gn = n0 + wn + nj * 8 + 2 * c;
            *(float2*)&C[(size_t)gm * C_ + gn]       = make_float2(acc[mi][nj].x, acc[mi][nj].y);
            *(float2*)&C[(size_t)(gm + 8) * C_ + gn] = make_float2(acc[mi][nj].z, acc[mi][nj].w);
        }
}

// ---------------------------------------------------------------------------
// Scores -> store UNNORMALIZED exp(0.125*QK) (masked->0) + row partial sums.
// 2-term. grid (16, 16, 24)
// ---------------------------------------------------------------------------
__global__ void __launch_bounds__(256) scores_tc(const float* __restrict__ Q,
                                                 const float* __restrict__ Kt,
                                                 float* __restrict__ W,
                                                 float* __restrict__ partial) {
    const int z = blockIdx.z;
    const int b = z / H_, h = z % H_;
    const int m0 = blockIdx.y * 128, n0 = blockIdx.x * 128;
    const int tid = threadIdx.x;
    float* Cz = W + (size_t)z * T_ * T_;

    if (n0 > m0) {
        const float4 zz = make_float4(0, 0, 0, 0);
        for (int idx = tid; idx < 128 * 32; idx += 256) {
            int row = idx >> 5, c4 = (idx & 31) << 2;
            *(float4*)&Cz[(size_t)(m0 + row) * T_ + n0 + c4] = zz;
        }
        return;
    }

    __shared__ float As[2][128][SKF], Bs[2][128][SKF];
    __shared__ float spart[128][4];
    const int warp = tid >> 5, lane = tid & 31;
    const int wm = (warp >> 2) * 64, wn = (warp & 3) * 32;
    const int r = lane >> 2, c = lane & 3;
    const float* Ap = Q + (size_t)b * T_ * C_ + h * DH_;
    const float* Bp = Kt + (size_t)b * T_ * C_ + h * DH_;
    const int row0 = tid >> 2, ko0 = (tid & 3) << 2;
    const int row1 = row0 + 64;

    float4 acc[4][4];
#pragma unroll
    for (int i = 0; i < 4; i++)
#pragma unroll
        for (int j = 0; j < 4; j++) acc[i][j] = make_float4(0, 0, 0, 0);

    cp16(&As[0][row0][ko0], Ap + (size_t)(m0 + row0) * C_ + ko0);
    cp16(&As[0][row1][ko0], Ap + (size_t)(m0 + row1) * C_ + ko0);
    cp16(&Bs[0][row0][ko0], Bp + (size_t)(n0 + row0) * C_ + ko0);
    cp16(&Bs[0][row1][ko0], Bp + (size_t)(n0 + row1) * C_ + ko0);
    CP_COMMIT;

#pragma unroll
    for (int it = 0; it < DH_ / 16; it++) {
        if (it + 1 < DH_ / 16) {
            int kn = (it + 1) * 16;
            int s = (it + 1) & 1;
            cp16(&As[s][row0][ko0], Ap + (size_t)(m0 + row0) * C_ + kn + ko0);
            cp16(&As[s][row1][ko0], Ap + (size_t)(m0 + row1) * C_ + kn + ko0);
            cp16(&Bs[s][row0][ko0], Bp + (size_t)(n0 + row0) * C_ + kn + ko0);
            cp16(&Bs[s][row1][ko0], Bp + (size_t)(n0 + row1) * C_ + kn + ko0);
            CP_COMMIT;
            CP_WAIT1;
        } else {
            CP_WAIT0;
        }
        __syncthreads();
        const float (*Af)[SKF] = As[it & 1];
        const float (*Bf)[SKF] = Bs[it & 1];
#pragma unroll
        for (int kb = 0; kb < 16; kb += 8) {
            uint32_t bh[4][2];
#pragma unroll
            for (int nj = 0; nj < 4; nj++) {
                int col = wn + nj * 8 + r;
                bh[nj][0] = f2tf(Bf[col][kb + c]);
                bh[nj][1] = f2tf(Bf[col][kb + c + 4]);
            }
#pragma unroll
            for (int mi = 0; mi < 4; mi++) {
                int rw = wm + mi * 16 + r;
                uint32_t ah[4], al[4];
                split_lo(Af[rw][kb + c],         ah[0], al[0]);
                split_lo(Af[rw + 8][kb + c],     ah[1], al[1]);
                split_lo(Af[rw][kb + c + 4],     ah[2], al[2]);
                split_lo(Af[rw + 8][kb + c + 4], ah[3], al[3]);
#pragma unroll
                for (int nj = 0; nj < 4; nj++) {
                    mma8(acc[mi][nj], al, bh[nj]);
                    mma8(acc[mi][nj], ah, bh[nj]);
                }
            }
        }
        __syncthreads();
    }

    const bool diag = (n0 == m0);
#pragma unroll
    for (int mi = 0; mi < 4; mi++) {
        float se0 = 0.0f, se1 = 0.0f;
        int gm = m0 + wm + mi * 16 + r;
#pragma unroll
        for (int nj = 0; nj < 4; nj++) {
            int gn = n0 + wn + nj * 8 + 2 * c;
            float e0 = exp2f(0.125f * LOG2E * acc[mi][nj].x);
            float e1 = exp2f(0.125f * LOG2E * acc[mi][nj].y);
            float e2 = exp2f(0.125f * LOG2E * acc[mi][nj].z);
            float e3 = exp2f(0.125f * LOG2E * acc[mi][nj].w);
            if (diag) {
                if (gn > gm) e0 = 0.0f;
                if (gn + 1 > gm) e1 = 0.0f;
                if (gn > gm + 8) e2 = 0.0f;
                if (gn + 1 > gm + 8) e3 = 0.0f;
            }
            se0 += e0 + e1;
            se1 += e2 + e3;
            *(float2*)&Cz[(size_t)gm * T_ + gn]       = make_float2(e0, e1);
            *(float2*)&Cz[(size_t)(gm + 8) * T_ + gn] = make_float2(e2, e3);
        }
        se0 += __shfl_xor_sync(0xffffffffu, se0, 1);
        se0 += __shfl_xor_sync(0xffffffffu, se0, 2);
        se1 += __shfl_xor_sync(0xffffffffu, se1, 1);
        se1 += __shfl_xor_sync(0xffffffffu, se1, 2);
        if (c == 0) {
            spart[wm + mi * 16 + r][warp & 3]     = se0;
            spart[wm + mi * 16 + r + 8][warp & 3] = se1;
        }
    }
    __syncthreads();
    if (tid < 128) {
        float s = spart[tid][0] + spart[tid][1] + spart[tid][2] + spart[tid][3];
        partial[((size_t)z * T_ + m0 + tid) * 16 + (n0 >> 7)] = s;
    }
}

// ---------------------------------------------------------------------------
// invsum: reduce partials -> 1/rowsum. grid (192), 256 thr.
// ---------------------------------------------------------------------------
__global__ void __launch_bounds__(256) invsum_kernel(const float* __restrict__ partial,
                                                     float* __restrict__ invsum) {
    const int rg = blockIdx.x * 256 + threadIdx.x;
    const int i = rg % T_;
    const int ntmax = i >> 7;
    float s = 0.0f;
    const float* p = partial + (size_t)rg * 16;
    for (int nt = 0; nt <= ntmax; nt++) s += p[nt];
    invsum[rg] = 1.0f / s;
}

// ---------------------------------------------------------------------------
// Normalize weights in place (reads invsum). One block (128 thr) per row.
// Runs on side stream, overlapped with pv_reduce + gemm_final.
// ---------------------------------------------------------------------------
__global__ void __launch_bounds__(128) normalize_kernel(float* __restrict__ W,
                                                        const float* __restrict__ invsum) {
    const int rg = blockIdx.x;
    const int i = rg % T_;
    const float il = invsum[rg];
    const int n4 = (i + 4) >> 2;
    float4* row = (float4*)(W + (size_t)rg * T_);
    for (int j = threadIdx.x; j < n4; j += 128) {
        float4 v = row[j];
        v.x *= il; v.y *= il; v.z *= il; v.w *= il;
        row[j] = v;
    }
}

// ---------------------------------------------------------------------------
// PV k-split, 2-term, reads UNNORMALIZED e; scales acc by invsum in epilogue.
// grid (4, 16, 24), mt reversed.
// ---------------------------------------------------------------------------
__global__ void __launch_bounds__(256, 4) pv_split_tc(const float* __restrict__ W,
                                                      const float* __restrict__ V,
                                                      float* __restrict__ part,
                                                      const float* __restrict__ invsum) {
    const int ck = blockIdx.x;
    const int mt = 15 - blockIdx.y;
    const int z = blockIdx.z;
    const int m0 = mt * 128;
    const int kbeg = ck * 512;
    const int kend = min(kbeg + 512, m0 + 128);
    if (kbeg >= kend) return;

    const int b = z / H_, h = z % H_;
    const int tid = threadIdx.x;
    const int warp = tid >> 5, lane = tid & 31;
    const int wm = (warp >> 2) * 64, wn = (warp & 3) * 16;
    const int r = lane >> 2, c = lane & 3;

    const float* Wz = W + (size_t)z * T_ * T_;
    const float* Vp = V + (size_t)b * T_ * C_ + h * DH_;

    __shared__ float As[2][128][SKF];
    __shared__ float Vs[2][16][SVF];
    __shared__ float ils[128];

    if (tid < 128) ils[tid] = invsum[(size_t)z * T_ + m0 + tid];

    const int row0 = tid >> 2, ko0 = (tid & 3) << 2;
    const int row1 = row0 + 64;
    const int kr = tid >> 4, nc = (tid & 15) << 2;

    float4 acc[4][2];
#pragma unroll
    for (int i = 0; i < 4; i++)
#pragma unroll
        for (int j = 0; j < 2; j++) acc[i][j] = make_float4(0, 0, 0, 0);

    const int niter = (kend - kbeg) / 16;
    cp16(&As[0][row0][ko0], Wz + (size_t)(m0 + row0) * T_ + kbeg + ko0);
    cp16(&As[0][row1][ko0], Wz + (size_t)(m0 + row1) * T_ + kbeg + ko0);
    cp16(&Vs[0][kr][nc],    Vp + (size_t)(kbeg + kr) * C_ + nc);
    CP_COMMIT;

    for (int it = 0; it < niter; it++) {
        if (it + 1 < niter) {
            int kn = kbeg + (it + 1) * 16;
            int s = (it + 1) & 1;
            cp16(&As[s][row0][ko0], Wz + (size_t)(m0 + row0) * T_ + kn + ko0);
            cp16(&As[s][row1][ko0], Wz + (size_t)(m0 + row1) * T_ + kn + ko0);
            cp16(&Vs[s][kr][nc],    Vp + (size_t)(kn + kr) * C_ + nc);
            CP_COMMIT;
            CP_WAIT1;
        } else {
            CP_WAIT0;
        }
        __syncthreads();
        const float (*Af)[SKF] = As[it & 1];
        const float (*Vf)[SVF] = Vs[it & 1];
#pragma unroll
        for (int kb = 0; kb < 16; kb += 8) {
            uint32_t bh[2][2];
#pragma unroll
            for (int nj = 0; nj < 2; nj++) {
                int col = wn + nj * 8 + r;
                bh[nj][0] = f2tf(Vf[kb + c][col]);
                bh[nj][1] = f2tf(Vf[kb + c + 4][col]);
            }
#pragma unroll
            for (int mi = 0; mi < 4; mi++) {
                int rw = wm + mi * 16 + r;
                uint32_t ah[4], al[4];
                split_lo(Af[rw][kb + c],         ah[0], al[0]);
                split_lo(Af[rw + 8][kb + c],     ah[1], al[1]);
                split_lo(Af[rw][kb + c + 4],     ah[2], al[2]);
                split_lo(Af[rw + 8][kb + c + 4], ah[3], al[3]);
#pragma unroll
                for (int nj = 0; nj < 2; nj++) {
                    mma8(acc[mi][nj], al, bh[nj]);
                    mma8(acc[mi][nj], ah, bh[nj]);
                }
            }
        }
        __syncthreads();
    }

    float* P = part + ((size_t)(z * 16 + mt) * 4 + ck) * (128 * DH_);
#pragma unroll
    for (int mi = 0; mi < 4; mi++)
#pragma unroll
        for (int nj = 0; nj < 2; nj++) {
            int lr = wm + mi * 16 + r;
            int gn = wn + nj * 8 + 2 * c;
            float il0 = ils[lr], il1 = ils[lr + 8];
            *(float2*)&P[(size_t)lr * DH_ + gn] =
                make_float2(acc[mi][nj].x * il0, acc[mi][nj].y * il0);
            *(float2*)&P[(size_t)(lr + 8) * DH_ + gn] =
                make_float2(acc[mi][nj].z * il1, acc[mi][nj].w * il1);
        }
}

// ---------------------------------------------------------------------------
// Sum pv partials -> O (g_att layout [B,T,C]). grid (384), 256 thr.
// ---------------------------------------------------------------------------
__global__ void __launch_bounds__(256) pv_reduce(const float* __restrict__ part,
                                                 float* __restrict__ O) {
    const int blk = blockIdx.x;
    const int z = blk >> 4, mt = blk & 15;
    const int b = z / H_, h = z % H_;
    const int m0 = mt * 128;
    const int nch = (mt >> 2) + 1;
    const float* p = part + (size_t)blk * 4 * (128 * DH_);

    for (int idx = threadIdx.x * 4; idx < 128 * DH_; idx += 256 * 4) {
        float4 s = *(const float4*)(p + idx);
        for (int c2 = 1; c2 < nch; c2++) {
            float4 t = *(const float4*)(p + (size_t)c2 * 128 * DH_ + idx);
            s.x += t.x; s.y += t.y; s.z += t.z; s.w += t.w;
        }
        const int row = idx >> 6, n = idx & 63;
        *(float4*)&O[(size_t)(b * T_ + m0 + row) * C_ + h * DH_ + n] = s;
    }
}

// ---------------------------------------------------------------------------
extern "C" void kernel_launch(void* const* d_in, const int* in_sizes, int n_in,
                              void* d_out, int out_size) {
    const float* x   = (const float*)d_in[0];
    const float* w_q = (const float*)d_in[1];
    const float* w_k = (const float*)d_in[2];
    const float* w_v = (const float*)d_in[3];
    const float* w_o = (const float*)d_in[4];

    float* qp; cudaGetSymbolAddress((void**)&qp, g_q);
    float* kp; cudaGetSymbolAddress((void**)&kp, g_k);
    float* vp; cudaGetSymbolAddress((void**)&vp, g_v);
    float* ap; cudaGetSymbolAddress((void**)&ap, g_att);
    float* pp; cudaGetSymbolAddress((void**)&pp, g_partial);
    float* ip; cudaGetSymbolAddress((void**)&ip, g_invsum);
    float* vv; cudaGetSymbolAddress((void**)&vv, g_pvpart);

    float* final_out = (float*)d_out;                       // [B,T,C]
    float* w_out = (float*)d_out + (size_t)B_ * T_ * C_;    // [B,H,T,T]

    static cudaStream_t s2;
    static cudaEvent_t ev_fork, ev_join;
    static int init = 0;
    if (!init) {
        cudaStreamCreateWithFlags(&s2, cudaStreamNonBlocking);
        cudaEventCreateWithFlags(&ev_fork, cudaEventDisableTiming);
        cudaEventCreateWithFlags(&ev_join, cudaEventDisableTiming);
        init = 1;
    }

    const dim3 blk(256);

    gemm_qkv<<<dim3(18, 32), blk>>>(x, w_q, w_k, w_v, qp, kp, vp);

    scores_tc<<<dim3(T_ / 128, T_ / 128, B_ * H_), blk>>>(qp, kp, w_out, pp);

    invsum_kernel<<<(B_ * H_ * T_) / 256, blk>>>(pp, ip);

    pv_split_tc<<<dim3(4, 16, 24), blk>>>(w_out, vp, vv, ip);

    // Fork: normalize (weights output scaling) runs on side stream, overlapped
    // with pv_reduce + final projection (disjoint memory).
    cudaEventRecord(ev_fork, 0);
    cudaStreamWaitEvent(s2, ev_fork, 0);
    normalize_kernel<<<B_ * H_ * T_, 128, 0, s2>>>(w_out, ip);
    cudaEventRecord(ev_join, s2);

    pv_reduce<<<B_ * H_ * 16, blk>>>(vv, ap);

    gemm_final64<<<dim3(12, 32), blk>>>(ap, w_o, final_out);

    // Join before capture ends.
    cudaStreamWaitEvent(0, ev_join, 0);
}

// round 16
// speedup vs baseline: 1.2024x; 1.0715x over previous
#include <cuda_runtime.h>
#include <math.h>
#include <stdint.h>

#define B_   2
#define T_   2048
#define C_   768
#define H_   12
#define DH_  64
#define LOG2E 1.4426950408889634f
#define SKF  20   // float row stride (16 data + 4 pad) -> conflict-free frag LDS
#define SVF  72   // V k-major row stride (64 data + 8 pad)

// Scratch (device globals — no allocation allowed)
__device__ float g_q[B_ * T_ * C_];
__device__ float g_k[B_ * T_ * C_];
__device__ float g_v[B_ * T_ * C_];
__device__ float g_att[B_ * T_ * C_];
__device__ float g_partial[B_ * H_ * T_ * 16];
__device__ float g_invsum[B_ * H_ * T_];
__device__ float g_pvpart[B_ * H_ * 16 * 4 * 128 * DH_];

// ---------------------------------------------------------------------------
__device__ __forceinline__ uint32_t f2tf(float v) {
    uint32_t r;
    asm("cvt.rna.tf32.f32 %0, %1;" : "=r"(r) : "f"(v));
    return r;
}
__device__ __forceinline__ void mma8(float4& d, const uint32_t* a, const uint32_t* b) {
    asm("mma.sync.aligned.m16n8k8.row.col.f32.tf32.tf32.f32 "
        "{%0,%1,%2,%3}, {%4,%5,%6,%7}, {%8,%9}, {%0,%1,%2,%3};"
        : "+f"(d.x), "+f"(d.y), "+f"(d.z), "+f"(d.w)
        : "r"(a[0]), "r"(a[1]), "r"(a[2]), "r"(a[3]), "r"(b[0]), "r"(b[1]));
}
__device__ __forceinline__ void split_lo(float v, uint32_t& hi, uint32_t& lo) {
    hi = __float_as_uint(v);
    lo = __float_as_uint(v - __uint_as_float(hi & 0xFFFFE000u));
}
__device__ __forceinline__ void cp16(void* smem_dst, const void* gsrc) {
    uint32_t s = (uint32_t)__cvta_generic_to_shared(smem_dst);
    asm volatile("cp.async.cg.shared.global [%0], [%1], 16;" :: "r"(s), "l"(gsrc));
}
#define CP_COMMIT asm volatile("cp.async.commit_group;")
#define CP_WAIT1  asm volatile("cp.async.wait_group 1;")
#define CP_WAIT0  asm volatile("cp.async.wait_group 0;")

// ---------------------------------------------------------------------------
// 2-term NT GEMM (A exact hi+lo split, B rounded hi-only), cp.async pipeline.
// ---------------------------------------------------------------------------
__device__ __forceinline__ void gemm2_body(const float* __restrict__ A,
                                           const float* __restrict__ Bm,
                                           float* __restrict__ C,
                                           int K, int lda, int ldb, int ldc,
                                           int m0, int n0) {
    __shared__ float As[2][128][SKF], Bs[2][128][SKF];
    const int tid = threadIdx.x;
    const int warp = tid >> 5, lane = tid & 31;
    const int wm = (warp >> 2) * 64, wn = (warp & 3) * 32;
    const int r = lane >> 2, c = lane & 3;
    const int row0 = tid >> 2, ko0 = (tid & 3) << 2;
    const int row1 = row0 + 64;

    float4 acc[4][4];
#pragma unroll
    for (int i = 0; i < 4; i++)
#pragma unroll
        for (int j = 0; j < 4; j++) acc[i][j] = make_float4(0, 0, 0, 0);

    const int niter = K / 16;
    cp16(&As[0][row0][ko0], A + (size_t)(m0 + row0) * lda + ko0);
    cp16(&As[0][row1][ko0], A + (size_t)(m0 + row1) * lda + ko0);
    cp16(&Bs[0][row0][ko0], Bm + (size_t)(n0 + row0) * ldb + ko0);
    cp16(&Bs[0][row1][ko0], Bm + (size_t)(n0 + row1) * ldb + ko0);
    CP_COMMIT;

    for (int it = 0; it < niter; it++) {
        if (it + 1 < niter) {
            int kn = (it + 1) * 16;
            int s = (it + 1) & 1;
            cp16(&As[s][row0][ko0], A + (size_t)(m0 + row0) * lda + kn + ko0);
            cp16(&As[s][row1][ko0], A + (size_t)(m0 + row1) * lda + kn + ko0);
            cp16(&Bs[s][row0][ko0], Bm + (size_t)(n0 + row0) * ldb + kn + ko0);
            cp16(&Bs[s][row1][ko0], Bm + (size_t)(n0 + row1) * ldb + kn + ko0);
            CP_COMMIT;
            CP_WAIT1;
        } else {
            CP_WAIT0;
        }
        __syncthreads();
        const float (*Af)[SKF] = As[it & 1];
        const float (*Bf)[SKF] = Bs[it & 1];
#pragma unroll
        for (int kb = 0; kb < 16; kb += 8) {
            uint32_t bh[4][2];
#pragma unroll
            for (int nj = 0; nj < 4; nj++) {
                int col = wn + nj * 8 + r;
                bh[nj][0] = f2tf(Bf[col][kb + c]);
                bh[nj][1] = f2tf(Bf[col][kb + c + 4]);
            }
#pragma unroll
            for (int mi = 0; mi < 4; mi++) {
                int rw = wm + mi * 16 + r;
                uint32_t ah[4], al[4];
                split_lo(Af[rw][kb + c],         ah[0], al[0]);
                split_lo(Af[rw + 8][kb + c],     ah[1], al[1]);
                split_lo(Af[rw][kb + c + 4],     ah[2], al[2]);
                split_lo(Af[rw + 8][kb + c + 4], ah[3], al[3]);
#pragma unroll
                for (int nj = 0; nj < 4; nj++) {
                    mma8(acc[mi][nj], al, bh[nj]);
                    mma8(acc[mi][nj], ah, bh[nj]);
                }
            }
        }
        __syncthreads();
    }
#pragma unroll
    for (int mi = 0; mi < 4; mi++)
#pragma unroll
        for (int nj = 0; nj < 4; nj++) {
            int gm = m0 + wm + mi * 16 + r;
            int gn = n0 + wn + nj * 8 + 2 * c;
            *(float2*)&C[(size_t)gm * ldc + gn]       = make_float2(acc[mi][nj].x, acc[mi][nj].y);
            *(float2*)&C[(size_t)(gm + 8) * ldc + gn] = make_float2(acc[mi][nj].z, acc[mi][nj].w);
        }
}

// Fused QKV projection (2-term): grid (18, 32)
__global__ void __launch_bounds__(256) gemm_qkv(const float* __restrict__ x,
                                                const float* __restrict__ wq,
                                                const float* __restrict__ wk,
                                                const float* __restrict__ wv,
                                                float* __restrict__ q,
                                                float* __restrict__ k,
                                                float* __restrict__ v) {
    const int nb = blockIdx.x;
    const int sel = nb / 6;
    const int n0 = (nb % 6) * 128;
    const int m0 = blockIdx.y * 128;
    const float* W = (sel == 0) ? wq : (sel == 1) ? wk : wv;
    float* O = (sel == 0) ? q : (sel == 1) ? k : v;
    gemm2_body(x, W, O, C_, C_, C_, C_, m0, n0);
}

// ---------------------------------------------------------------------------
// Final projection, 128x64 tiles (2-term): grid (12, 32). 8 warps as 4x2.
// ---------------------------------------------------------------------------
__global__ void __launch_bounds__(256) gemm_final64(const float* __restrict__ A,
                                                    const float* __restrict__ Wo,
                                                    float* __restrict__ C) {
    __shared__ float As[2][128][SKF], Bs[2][64][SKF];
    const int m0 = blockIdx.y * 128, n0 = blockIdx.x * 64;
    const int tid = threadIdx.x;
    const int warp = tid >> 5, lane = tid & 31;
    const int wm = (warp >> 1) * 32, wn = (warp & 1) * 32;
    const int r = lane >> 2, c = lane & 3;
    const int row0 = tid >> 2, ko0 = (tid & 3) << 2;
    const int row1 = row0 + 64;

    float4 acc[2][4];
#pragma unroll
    for (int i = 0; i < 2; i++)
#pragma unroll
        for (int j = 0; j < 4; j++) acc[i][j] = make_float4(0, 0, 0, 0);

    const int niter = C_ / 16;
    cp16(&As[0][row0][ko0], A + (size_t)(m0 + row0) * C_ + ko0);
    cp16(&As[0][row1][ko0], A + (size_t)(m0 + row1) * C_ + ko0);
    if (row0 < 64) cp16(&Bs[0][row0][ko0], Wo + (size_t)(n0 + row0) * C_ + ko0);
    CP_COMMIT;

    for (int it = 0; it < niter; it++) {
        if (it + 1 < niter) {
            int kn = (it + 1) * 16;
            int s = (it + 1) & 1;
            cp16(&As[s][row0][ko0], A + (size_t)(m0 + row0) * C_ + kn + ko0);
            cp16(&As[s][row1][ko0], A + (size_t)(m0 + row1) * C_ + kn + ko0);
            if (row0 < 64) cp16(&Bs[s][row0][ko0], Wo + (size_t)(n0 + row0) * C_ + kn + ko0);
            CP_COMMIT;
            CP_WAIT1;
        } else {
            CP_WAIT0;
        }
        __syncthreads();
        const float (*Af)[SKF] = As[it & 1];
        const float (*Bf)[SKF] = Bs[it & 1];
#pragma unroll
        for (int kb = 0; kb < 16; kb += 8) {
            uint32_t bh[4][2];
#pragma unroll
            for (int nj = 0; nj < 4; nj++) {
                int col = wn + nj * 8 + r;
                bh[nj][0] = f2tf(Bf[col][kb + c]);
                bh[nj][1] = f2tf(Bf[col][kb + c + 4]);
            }
#pragma unroll
            for (int mi = 0; mi < 2; mi++) {
                int rw = wm + mi * 16 + r;
                uint32_t ah[4], al[4];
                split_lo(Af[rw][kb + c],         ah[0], al[0]);
                split_lo(Af[rw + 8][kb + c],     ah[1], al[1]);
                split_lo(Af[rw][kb + c + 4],     ah[2], al[2]);
                split_lo(Af[rw + 8][kb + c + 4], ah[3], al[3]);
#pragma unroll
                for (int nj = 0; nj < 4; nj++) {
                    mma8(acc[mi][nj], al, bh[nj]);
                    mma8(acc[mi][nj], ah, bh[nj]);
                }
            }
        }
        __syncthreads();
    }
#pragma unroll
    for (int mi = 0; mi < 2; mi++)
#pragma unroll
        for (int nj = 0; nj < 4; nj++) {
            int gm = m0 + wm + mi * 16 + r;
            int gn = n0 + wn + nj * 8 + 2 * c;
            *(float2*)&C[(size_t)gm * C_ + gn]       = make_float2(acc[mi][nj].x, acc[mi][nj].y);
            *(float2*)&C[(size_t)(gm + 8) * C_ + gn] = make_float2(acc[mi][nj].z, acc[mi][nj].w);
        }
}

// ---------------------------------------------------------------------------
// Zero-fill fully-masked weight tiles (nt > mt). grid (120, 24). No deps.
// ---------------------------------------------------------------------------
__global__ void __launch_bounds__(256) zero_fill(float* __restrict__ W) {
    const int i = blockIdx.x;              // 0..119 -> (mt, nt), nt > mt
    int mt = 0;
    while (15 * (mt + 1) - ((mt + 1) * mt) / 2 <= i) mt++;
    const int nt = mt + 1 + (i - (15 * mt - (mt * (mt - 1)) / 2));
    const int z = blockIdx.y;
    float* Cz = W + (size_t)z * T_ * T_ + (size_t)(mt * 128) * T_ + nt * 128;
    const float4 zz = make_float4(0, 0, 0, 0);
    const int tid = threadIdx.x;
#pragma unroll
    for (int it = 0; it < 16; it++) {
        int idx = tid + it * 256;          // 4096 float4s = 128 rows x 32
        int row = idx >> 5, c4 = (idx & 31) << 2;
        *(float4*)&Cz[(size_t)row * T_ + c4] = zz;
    }
}

// ---------------------------------------------------------------------------
// Scores over live (lower-triangle + diag) tiles only. grid (136, 24).
// Stores UNNORMALIZED exp(0.125*QK) (masked->0) + row partial sums. 2-term.
// ---------------------------------------------------------------------------
__global__ void __launch_bounds__(256) scores_tc(const float* __restrict__ Q,
                                                 const float* __restrict__ Kt,
                                                 float* __restrict__ W,
                                                 float* __restrict__ partial) {
    const int li = blockIdx.x;             // 0..135 -> (mtile, ntile), n <= m
    int mtile = (int)((__fsqrt_rn(8.0f * li + 1.0f) - 1.0f) * 0.5f);
    while ((mtile + 1) * (mtile + 2) / 2 <= li) mtile++;
    while (mtile * (mtile + 1) / 2 > li) mtile--;
    const int ntile = li - mtile * (mtile + 1) / 2;
    const int m0 = mtile * 128, n0 = ntile * 128;
    const int z = blockIdx.y;
    const int b = z / H_, h = z % H_;
    const int tid = threadIdx.x;
    float* Cz = W + (size_t)z * T_ * T_;

    __shared__ float As[2][128][SKF], Bs[2][128][SKF];
    __shared__ float spart[128][4];
    const int warp = tid >> 5, lane = tid & 31;
    const int wm = (warp >> 2) * 64, wn = (warp & 3) * 32;
    const int r = lane >> 2, c = lane & 3;
    const float* Ap = Q + (size_t)b * T_ * C_ + h * DH_;
    const float* Bp = Kt + (size_t)b * T_ * C_ + h * DH_;
    const int row0 = tid >> 2, ko0 = (tid & 3) << 2;
    const int row1 = row0 + 64;

    float4 acc[4][4];
#pragma unroll
    for (int i = 0; i < 4; i++)
#pragma unroll
        for (int j = 0; j < 4; j++) acc[i][j] = make_float4(0, 0, 0, 0);

    cp16(&As[0][row0][ko0], Ap + (size_t)(m0 + row0) * C_ + ko0);
    cp16(&As[0][row1][ko0], Ap + (size_t)(m0 + row1) * C_ + ko0);
    cp16(&Bs[0][row0][ko0], Bp + (size_t)(n0 + row0) * C_ + ko0);
    cp16(&Bs[0][row1][ko0], Bp + (size_t)(n0 + row1) * C_ + ko0);
    CP_COMMIT;

#pragma unroll
    for (int it = 0; it < DH_ / 16; it++) {
        if (it + 1 < DH_ / 16) {
            int kn = (it + 1) * 16;
            int s = (it + 1) & 1;
            cp16(&As[s][row0][ko0], Ap + (size_t)(m0 + row0) * C_ + kn + ko0);
            cp16(&As[s][row1][ko0], Ap + (size_t)(m0 + row1) * C_ + kn + ko0);
            cp16(&Bs[s][row0][ko0], Bp + (size_t)(n0 + row0) * C_ + kn + ko0);
            cp16(&Bs[s][row1][ko0], Bp + (size_t)(n0 + row1) * C_ + kn + ko0);
            CP_COMMIT;
            CP_WAIT1;
        } else {
            CP_WAIT0;
        }
        __syncthreads();
        const float (*Af)[SKF] = As[it & 1];
        const float (*Bf)[SKF] = Bs[it & 1];
#pragma unroll
        for (int kb = 0; kb < 16; kb += 8) {
            uint32_t bh[4][2];
#pragma unroll
            for (int nj = 0; nj < 4; nj++) {
                int col = wn + nj * 8 + r;
                bh[nj][0] = f2tf(Bf[col][kb + c]);
                bh[nj][1] = f2tf(Bf[col][kb + c + 4]);
            }
#pragma unroll
            for (int mi = 0; mi < 4; mi++) {
                int rw = wm + mi * 16 + r;
                uint32_t ah[4], al[4];
                split_lo(Af[rw][kb + c],         ah[0], al[0]);
                split_lo(Af[rw + 8][kb + c],     ah[1], al[1]);
                split_lo(Af[rw][kb + c + 4],     ah[2], al[2]);
                split_lo(Af[rw + 8][kb + c + 4], ah[3], al[3]);
#pragma unroll
                for (int nj = 0; nj < 4; nj++) {
                    mma8(acc[mi][nj], al, bh[nj]);
                    mma8(acc[mi][nj], ah, bh[nj]);
                }
            }
        }
        __syncthreads();
    }

    const bool diag = (n0 == m0);
#pragma unroll
    for (int mi = 0; mi < 4; mi++) {
        float se0 = 0.0f, se1 = 0.0f;
        int gm = m0 + wm + mi * 16 + r;
#pragma unroll
        for (int nj = 0; nj < 4; nj++) {
            int gn = n0 + wn + nj * 8 + 2 * c;
            float e0 = exp2f(0.125f * LOG2E * acc[mi][nj].x);
            float e1 = exp2f(0.125f * LOG2E * acc[mi][nj].y);
            float e2 = exp2f(0.125f * LOG2E * acc[mi][nj].z);
            float e3 = exp2f(0.125f * LOG2E * acc[mi][nj].w);
            if (diag) {
                if (gn > gm) e0 = 0.0f;
                if (gn + 1 > gm) e1 = 0.0f;
                if (gn > gm + 8) e2 = 0.0f;
                if (gn + 1 > gm + 8) e3 = 0.0f;
            }
            se0 += e0 + e1;
            se1 += e2 + e3;
            *(float2*)&Cz[(size_t)gm * T_ + gn]       = make_float2(e0, e1);
            *(float2*)&Cz[(size_t)(gm + 8) * T_ + gn] = make_float2(e2, e3);
        }
        se0 += __shfl_xor_sync(0xffffffffu, se0, 1);
        se0 += __shfl_xor_sync(0xffffffffu, se0, 2);
        se1 += __shfl_xor_sync(0xffffffffu, se1, 1);
        se1 += __shfl_xor_sync(0xffffffffu, se1, 2);
        if (c == 0) {
            spart[wm + mi * 16 + r][warp & 3]     = se0;
            spart[wm + mi * 16 + r + 8][warp & 3] = se1;
        }
    }
    __syncthreads();
    if (tid < 128) {
        float s = spart[tid][0] + spart[tid][1] + spart[tid][2] + spart[tid][3];
        partial[((size_t)z * T_ + m0 + tid) * 16 + (n0 >> 7)] = s;
    }
}

// ---------------------------------------------------------------------------
// invsum: reduce partials -> 1/rowsum. grid (192), 256 thr.
// ---------------------------------------------------------------------------
__global__ void __launch_bounds__(256) invsum_kernel(const float* __restrict__ partial,
                                                     float* __restrict__ invsum) {
    const int rg = blockIdx.x * 256 + threadIdx.x;
    const int i = rg % T_;
    const int ntmax = i >> 7;
    float s = 0.0f;
    const float* p = partial + (size_t)rg * 16;
    for (int nt = 0; nt <= ntmax; nt++) s += p[nt];
    invsum[rg] = 1.0f / s;
}

// ---------------------------------------------------------------------------
// Normalize weights in place (reads invsum). One block (128 thr) per row.
// Runs on side stream, overlapped with pv_reduce + gemm_final.
// ---------------------------------------------------------------------------
__global__ void __launch_bounds__(128) normalize_kernel(float* __restrict__ W,
                                                        const float* __restrict__ invsum) {
    const int rg = blockIdx.x;
    const int i = rg % T_;
    const float il = invsum[rg];
    const int n4 = (i + 4) >> 2;
    float4* row = (float4*)(W + (size_t)rg * T_);
    for (int j = threadIdx.x; j < n4; j += 128) {
        float4 v = row[j];
        v.x *= il; v.y *= il; v.z *= il; v.w *= il;
        row[j] = v;
    }
}

// ---------------------------------------------------------------------------
// PV k-split, 1-term (P HW-truncated raw, V rounded); invsum scaling in
// epilogue. grid (4, 16, 24), mt reversed.
// ---------------------------------------------------------------------------
__global__ void __launch_bounds__(256, 4) pv_split_tc(const float* __restrict__ W,
                                                      const float* __restrict__ V,
                                                      float* __restrict__ part,
                                                      const float* __restrict__ invsum) {
    const int ck = blockIdx.x;
    const int mt = 15 - blockIdx.y;
    const int z = blockIdx.z;
    const int m0 = mt * 128;
    const int kbeg = ck * 512;
    const int kend = min(kbeg + 512, m0 + 128);
    if (kbeg >= kend) return;

    const int b = z / H_, h = z % H_;
    const int tid = threadIdx.x;
    const int warp = tid >> 5, lane = tid & 31;
    const int wm = (warp >> 2) * 64, wn = (warp & 3) * 16;
    const int r = lane >> 2, c = lane & 3;

    const float* Wz = W + (size_t)z * T_ * T_;
    const float* Vp = V + (size_t)b * T_ * C_ + h * DH_;

    __shared__ float As[2][128][SKF];
    __shared__ float Vs[2][16][SVF];
    __shared__ float ils[128];

    if (tid < 128) ils[tid] = invsum[(size_t)z * T_ + m0 + tid];

    const int row0 = tid >> 2, ko0 = (tid & 3) << 2;
    const int row1 = row0 + 64;
    const int kr = tid >> 4, nc = (tid & 15) << 2;

    float4 acc[4][2];
#pragma unroll
    for (int i = 0; i < 4; i++)
#pragma unroll
        for (int j = 0; j < 2; j++) acc[i][j] = make_float4(0, 0, 0, 0);

    const int niter = (kend - kbeg) / 16;
    cp16(&As[0][row0][ko0], Wz + (size_t)(m0 + row0) * T_ + kbeg + ko0);
    cp16(&As[0][row1][ko0], Wz + (size_t)(m0 + row1) * T_ + kbeg + ko0);
    cp16(&Vs[0][kr][nc],    Vp + (size_t)(kbeg + kr) * C_ + nc);
    CP_COMMIT;

    for (int it = 0; it < niter; it++) {
        if (it + 1 < niter) {
            int kn = kbeg + (it + 1) * 16;
            int s = (it + 1) & 1;
            cp16(&As[s][row0][ko0], Wz + (size_t)(m0 + row0) * T_ + kn + ko0);
            cp16(&As[s][row1][ko0], Wz + (size_t)(m0 + row1) * T_ + kn + ko0);
            cp16(&Vs[s][kr][nc],    Vp + (size_t)(kn + kr) * C_ + nc);
            CP_COMMIT;
            CP_WAIT1;
        } else {
            CP_WAIT0;
        }
        __syncthreads();
        const float (*Af)[SKF] = As[it & 1];
        const float (*Vf)[SVF] = Vs[it & 1];
#pragma unroll
        for (int kb = 0; kb < 16; kb += 8) {
            uint32_t bh[2][2];
#pragma unroll
            for (int nj = 0; nj < 2; nj++) {
                int col = wn + nj * 8 + r;
                bh[nj][0] = f2tf(Vf[kb + c][col]);
                bh[nj][1] = f2tf(Vf[kb + c + 4][col]);
            }
#pragma unroll
            for (int mi = 0; mi < 4; mi++) {
                int rw = wm + mi * 16 + r;
                uint32_t ah[4];   // raw fp32 bits; HW truncates to tf32
                ah[0] = __float_as_uint(Af[rw][kb + c]);
                ah[1] = __float_as_uint(Af[rw + 8][kb + c]);
                ah[2] = __float_as_uint(Af[rw][kb + c + 4]);
                ah[3] = __float_as_uint(Af[rw + 8][kb + c + 4]);
#pragma unroll
                for (int nj = 0; nj < 2; nj++)
                    mma8(acc[mi][nj], ah, bh[nj]);
            }
        }
        __syncthreads();
    }

    float* P = part + ((size_t)(z * 16 + mt) * 4 + ck) * (128 * DH_);
#pragma unroll
    for (int mi = 0; mi < 4; mi++)
#pragma unroll
        for (int nj = 0; nj < 2; nj++) {
            int lr = wm + mi * 16 + r;
            int gn = wn + nj * 8 + 2 * c;
            float il0 = ils[lr], il1 = ils[lr + 8];
            *(float2*)&P[(size_t)lr * DH_ + gn] =
                make_float2(acc[mi][nj].x * il0, acc[mi][nj].y * il0);
            *(float2*)&P[(size_t)(lr + 8) * DH_ + gn] =
                make_float2(acc[mi][nj].z * il1, acc[mi][nj].w * il1);
        }
}

// ---------------------------------------------------------------------------
// Sum pv partials -> O (g_att layout [B,T,C]). grid (384), 256 thr.
// ---------------------------------------------------------------------------
__global__ void __launch_bounds__(256) pv_reduce(const float* __restrict__ part,
                                                 float* __restrict__ O) {
    const int blk = blockIdx.x;
    const int z = blk >> 4, mt = blk & 15;
    const int b = z / H_, h = z % H_;
    const int m0 = mt * 128;
    const int nch = (mt >> 2) + 1;
    const float* p = part + (size_t)blk * 4 * (128 * DH_);

    for (int idx = threadIdx.x * 4; idx < 128 * DH_; idx += 256 * 4) {
        float4 s = *(const float4*)(p + idx);
        for (int c2 = 1; c2 < nch; c2++) {
            float4 t = *(const float4*)(p + (size_t)c2 * 128 * DH_ + idx);
            s.x += t.x; s.y += t.y; s.z += t.z; s.w += t.w;
        }
        const int row = idx >> 6, n = idx & 63;
        *(float4*)&O[(size_t)(b * T_ + m0 + row) * C_ + h * DH_ + n] = s;
    }
}

// ---------------------------------------------------------------------------
extern "C" void kernel_launch(void* const* d_in, const int* in_sizes, int n_in,
                              void* d_out, int out_size) {
    const float* x   = (const float*)d_in[0];
    const float* w_q = (const float*)d_in[1];
    const float* w_k = (const float*)d_in[2];
    const float* w_v = (const float*)d_in[3];
    const float* w_o = (const float*)d_in[4];

    float* qp; cudaGetSymbolAddress((void**)&qp, g_q);
    float* kp; cudaGetSymbolAddress((void**)&kp, g_k);
    float* vp; cudaGetSymbolAddress((void**)&vp, g_v);
    float* ap; cudaGetSymbolAddress((void**)&ap, g_att);
    float* pp; cudaGetSymbolAddress((void**)&pp, g_partial);
    float* ip; cudaGetSymbolAddress((void**)&ip, g_invsum);
    float* vv; cudaGetSymbolAddress((void**)&vv, g_pvpart);

    float* final_out = (float*)d_out;                       // [B,T,C]
    float* w_out = (float*)d_out + (size_t)B_ * T_ * C_;    // [B,H,T,T]

    static cudaStream_t s2;
    static cudaEvent_t ev_fork, ev_join;
    static int init = 0;
    if (!init) {
        cudaStreamCreateWithFlags(&s2, cudaStreamNonBlocking);
        cudaEventCreateWithFlags(&ev_fork, cudaEventDisableTiming);
        cudaEventCreateWithFlags(&ev_join, cudaEventDisableTiming);
        init = 1;
    }

    const dim3 blk(256);

    // Side stream: zero-fill masked weight tiles (no deps), overlapped with qkv.
    zero_fill<<<dim3(120, 24), blk, 0, s2>>>(w_out);

    gemm_qkv<<<dim3(18, 32), blk>>>(x, w_q, w_k, w_v, qp, kp, vp);

    scores_tc<<<dim3(136, 24), blk>>>(qp, kp, w_out, pp);

    invsum_kernel<<<(B_ * H_ * T_) / 256, blk>>>(pp, ip);

    pv_split_tc<<<dim3(4, 16, 24), blk>>>(w_out, vp, vv, ip);

    // Fork: normalize (weights scaling) on side stream, overlapped with
    // pv_reduce + final projection (disjoint memory).
    cudaEventRecord(ev_fork, 0);
    cudaStreamWaitEvent(s2, ev_fork, 0);
    normalize_kernel<<<B_ * H_ * T_, 128, 0, s2>>>(w_out, ip);
    cudaEventRecord(ev_join, s2);

    pv_reduce<<<B_ * H_ * 16, blk>>>(vv, ap);

    gemm_final64<<<dim3(12, 32), blk>>>(ap, w_o, final_out);

    // Join before capture ends.
    cudaStreamWaitEvent(0, ev_join, 0);
}